// round 7
// baseline (speedup 1.0000x reference)
#include <cuda_runtime.h>

#define IMG 28
#define PIX 784            // 28*28
#define QUADS 196          // 784/4 float4 per image
#define B_IMGS 65536
#define CENTER 14

__global__ __launch_bounds__(256)
void sr_restore_kernel(const float* __restrict__ x,
                       const int* __restrict__ t,
                       const float* __restrict__ Wk,
                       const float* __restrict__ bias,
                       float* __restrict__ out)
{
    // flat quad index; grid sized exactly: B_IMGS*QUADS / 256 blocks
    unsigned idx = blockIdx.x * blockDim.x + threadIdx.x;
    unsigned img  = idx / QUADS;
    unsigned quad = idx - img * QUADS;

    const float* ximg = x + (size_t)img * PIX;
    const float4 xv = *reinterpret_cast<const float4*>(ximg + quad * 4);

    int tv = __ldg(t + img);                  // 0..19
    int r2max = tv * tv;                      // in_t:    d2 <= t^2
    int r2min = (tv >= 1) ? (tv - 1) * (tv - 1) : -1;  // in_{t-1}: d2 <= (t-1)^2 (t>=1)

    float o[4] = {xv.x, xv.y, xv.z, xv.w};

    int p0 = quad * 4;
    bool m[4];
    bool need = false;
#pragma unroll
    for (int k = 0; k < 4; k++) {
        int p = p0 + k;
        int row = p / IMG;
        int col = p - row * IMG;
        int dr = row - CENTER, dc = col - CENTER;
        int d2 = dr * dr + dc * dc;
        m[k] = (d2 <= r2max) && (d2 > r2min);   // ring annulus
        need |= m[k];
    }

    if (need) {
        float w[9];
#pragma unroll
        for (int i = 0; i < 9; i++) w[i] = __ldg(Wk + i);
        float bb = __ldg(bias);

#pragma unroll
        for (int k = 0; k < 4; k++) {
            if (!m[k]) continue;
            int p = p0 + k;
            int row = p / IMG;
            int col = p - row * IMG;
            float acc = bb;
#pragma unroll
            for (int dr = -1; dr <= 1; dr++) {
#pragma unroll
                for (int dc = -1; dc <= 1; dc++) {
                    int rr = row + dr, cc = col + dc;
                    float xn = (rr >= 0 && rr < IMG && cc >= 0 && cc < IMG)
                                   ? ximg[rr * IMG + cc] : 0.0f;
                    acc = fmaf(w[(dr + 1) * 3 + (dc + 1)], xn, acc);
                }
            }
            o[k] += acc;   // out = x + x0 * ring
        }
    }

    float4 ov = make_float4(o[0], o[1], o[2], o[3]);
    *reinterpret_cast<float4*>(out + (size_t)img * PIX + quad * 4) = ov;
}

extern "C" void kernel_launch(void* const* d_in, const int* in_sizes, int n_in,
                              void* d_out, int out_size)
{
    const float* x    = (const float*)d_in[0];   // [65536,1,28,28] f32
    const int*   t    = (const int*)  d_in[1];   // [65536] i32
    const float* Wk   = (const float*)d_in[2];   // [1,1,3,3] f32
    const float* bias = (const float*)d_in[3];   // [1] f32
    float* out = (float*)d_out;

    const int total_quads = B_IMGS * QUADS;      // 12,845,056
    const int threads = 256;
    const int blocks = total_quads / threads;    // 50,176 (exact)

    sr_restore_kernel<<<blocks, threads>>>(x, t, Wk, bias, out);
}